// round 2
// baseline (speedup 1.0000x reference)
#include <cuda_runtime.h>
#include <stdint.h>

// AND-tree over last dim of (ROWS, 1024) binary float matrix.
// out[row] = 1.0f iff all 1024 elements == 1.0f (bit pattern 0x3F800000).
//
// Strategy: one warp per row. Each lane loads one 4-byte word -> the warp
// probes exactly one 128B cache line per iteration. __all_sync gives the AND
// across the warp. Early-exit as soon as any zero is seen: for uniform random
// bits the first 128B chunk resolves the row with prob 1 - 2^-32, cutting
// DRAM traffic from 256 MB to ~8 MB. Deterministic (data-dependent only).

static constexpr int ROW_LEN = 1024;           // floats per row
static constexpr int CHUNKS  = ROW_LEN / 32;   // 32 chunks of 128B per row
static constexpr unsigned ONE_BITS = 0x3F800000u;  // bit pattern of 1.0f

__global__ __launch_bounds__(256) void vec_and_tree_kernel(
    const unsigned* __restrict__ x, float* __restrict__ out, int rows)
{
    const int warp_id = (blockIdx.x * blockDim.x + threadIdx.x) >> 5;
    if (warp_id >= rows) return;
    const int lane = threadIdx.x & 31;

    const unsigned* rowp = x + (size_t)warp_id * ROW_LEN + lane;

    bool ok;
    int c = 0;
    #pragma unroll 1
    for (;;) {
        unsigned v = rowp[c * 32];
        ok = __all_sync(0xFFFFFFFFu, v == ONE_BITS);
        ++c;
        if (!ok || c == CHUNKS) break;   // almost always exits at c==1
    }

    if (lane == 0) out[warp_id] = ok ? 1.0f : 0.0f;
}

extern "C" void kernel_launch(void* const* d_in, const int* in_sizes, int n_in,
                              void* d_out, int out_size)
{
    const unsigned* x = (const unsigned*)d_in[0];   // float32 bits reinterpreted
    float* out = (float*)d_out;

    const int rows = out_size;                      // 65536 rows, one output each
    const int threads = 256;                        // 8 warps per block
    const int warps_per_block = threads / 32;
    const int blocks = (rows + warps_per_block - 1) / warps_per_block;

    vec_and_tree_kernel<<<blocks, threads>>>(x, out, rows);
}

// round 3
// speedup vs baseline: 1.3462x; 1.3462x over previous
#include <cuda_runtime.h>
#include <stdint.h>

// AND-tree over last dim of (ROWS, 1024) binary float matrix.
// out[row] = 1.0f iff all 1024 elements == 1.0f (bit pattern 0x3F800000).
//
// Latency-optimized: one THREAD per row (not one warp). Each thread probes
// the first 16B (uint4) of its row -> resolves the row with prob 15/16 on
// random bits, pulling only one 32B sector instead of a 128B line. Each
// thread handles R rows with all probe loads issued before any test (MLP=R).
// Survivors (1/16) rescan the row scalar with early exit (expected ~1 extra
// 16B load). Total DRAM traffic ~2.2MB; whole grid fits in one wave.

static constexpr int ROW_U4 = 1024 / 4;            // 256 uint4 per row
static constexpr unsigned ONE_BITS = 0x3F800000u;  // bit pattern of 1.0f
static constexpr int R = 2;                        // rows per thread
static constexpr int THREADS = 256;

__device__ __forceinline__ bool all_ones(uint4 v) {
    return v.x == ONE_BITS && v.y == ONE_BITS && v.z == ONE_BITS && v.w == ONE_BITS;
}

__global__ __launch_bounds__(THREADS) void vec_and_tree_kernel(
    const uint4* __restrict__ x, float* __restrict__ out, int rows)
{
    const int t = blockIdx.x * THREADS + threadIdx.x;
    const int T = gridDim.x * THREADS;   // total threads; rows == T * R when divisible

    // Phase 1: issue all probe loads up front (independent -> MLP = R).
    uint4 probe[R];
    int row[R];
    #pragma unroll
    for (int k = 0; k < R; k++) {
        row[k] = t + k * T;
        if (row[k] < rows)
            probe[k] = x[(size_t)row[k] * ROW_U4];
    }

    // Phase 2: test; rare survivors rescan the row with early exit.
    #pragma unroll
    for (int k = 0; k < R; k++) {
        if (row[k] >= rows) return;
        bool ok = all_ones(probe[k]);
        if (ok) {  // prob 1/16 per row on random bits
            const uint4* rp = x + (size_t)row[k] * ROW_U4;
            #pragma unroll 1
            for (int j = 1; j < ROW_U4; j++) {
                if (!all_ones(rp[j])) { ok = false; break; }
            }
        }
        out[row[k]] = ok ? 1.0f : 0.0f;
    }
}

extern "C" void kernel_launch(void* const* d_in, const int* in_sizes, int n_in,
                              void* d_out, int out_size)
{
    const uint4* x = (const uint4*)d_in[0];  // float32 bits reinterpreted
    float* out = (float*)d_out;

    const int rows = out_size;               // 65536 rows, one output each
    const int rows_per_block = THREADS * R;  // 512
    const int blocks = (rows + rows_per_block - 1) / rows_per_block;  // 128

    vec_and_tree_kernel<<<blocks, THREADS>>>(x, out, rows);
}